// round 4
// baseline (speedup 1.0000x reference)
#include <cuda_runtime.h>
#include <cuda_bf16.h>
#include <cstdint>

#define N_NODES 100000
#define DIM 128
#define NUM_LABELS 1024

// ---------------- scratch (no allocations allowed; float4 => 16B aligned) ----
__device__ float4 g_agg [ (size_t)N_NODES * (DIM/4) ];
__device__ float4 g_abuf[ (size_t)N_NODES * (DIM/4) ];
__device__ float4 g_h1  [ (size_t)N_NODES * (DIM/4) ];
__device__ float4 g_pool[ (size_t)N_NODES * (DIM/4) ];
__device__ int    g_idx64;

// ---------------- index-width detection (int32 vs int64 edge indices) -------
__global__ void detect_kernel(const unsigned long long* __restrict__ src) {
    if (threadIdx.x == 0 && blockIdx.x == 0) {
        int is64 = 1;
        for (int i = 0; i < 64; i++) {
            if (src[i] >> 32) { is64 = 0; break; }
        }
        g_idx64 = is64;
    }
}

// ---------------- zero kernel ----------------
__global__ void zero_kernel(float4* __restrict__ p, int n4) {
    int i = blockIdx.x * blockDim.x + threadIdx.x;
    int stride = gridDim.x * blockDim.x;
    float4 z = make_float4(0.f, 0.f, 0.f, 0.f);
    for (; i < n4; i += stride) p[i] = z;
}

// ---------------- scatter-add: one warp per edge ----------------
__global__ void scatter_kernel(const float4* __restrict__ h,
                               const void* __restrict__ srcv,
                               const void* __restrict__ dstv,
                               float* __restrict__ agg, int nE)
{
    int w = (blockIdx.x * blockDim.x + threadIdx.x) >> 5;
    int lane = threadIdx.x & 31;
    if (w >= nE) return;
    long long s, d;
    if (g_idx64) {
        s = ((const long long*)srcv)[w];
        d = ((const long long*)dstv)[w];
    } else {
        s = ((const int*)srcv)[w];
        d = ((const int*)dstv)[w];
    }
    float4 v = h[(size_t)s * 32 + lane];
    float* p = agg + (size_t)d * 128 + lane * 4;
    asm volatile("red.global.add.v4.f32 [%0], {%1,%2,%3,%4};"
                 :: "l"(p), "f"(v.x), "f"(v.y), "f"(v.z), "f"(v.w) : "memory");
}

// ======================= mma.sync bf16-split fused GEMM =======================
//   MODE_GIN      : A' = (1+eps)*A + AGG ;  out = relu(acc + b)
//   MODE_RES      : A' = A ;               out = A[m][n] + relu(acc + b)
//   MODE_RES_POOL : A' = A ;               out = 0.5*(H1[m][n] + A[m][n] + relu(acc+b))
//   MODE_FINAL    : A' = A ;               out = acc + b
#define MODE_GIN 0
#define MODE_RES 1
#define MODE_RES_POOL 2
#define MODE_FINAL 3

#define KC 32                 // k per smem chunk
#define SROW 20               // row stride in u32 (16 data + 4 pad) => conflict-free frags
#define TILE_U32 (128 * SROW) // 2560 u32 = 10240 B per bf16 tile

// split x into bf16 hi + bf16 lo packed pairwise: r = (y<<16)|x
__device__ __forceinline__ void split2(float x, float y, uint32_t& hi, uint32_t& lo) {
    __nv_bfloat16 hx = __float2bfloat16(x);
    __nv_bfloat16 hy = __float2bfloat16(y);
    __nv_bfloat16 lx = __float2bfloat16(x - __bfloat162float(hx));
    __nv_bfloat16 ly = __float2bfloat16(y - __bfloat162float(hy));
    hi = ((uint32_t)__bfloat16_as_ushort(hy) << 16) | (uint32_t)__bfloat16_as_ushort(hx);
    lo = ((uint32_t)__bfloat16_as_ushort(ly) << 16) | (uint32_t)__bfloat16_as_ushort(lx);
}

__device__ __forceinline__ void mma_bf16(float* d, const uint32_t* a, const uint32_t* b) {
    asm volatile(
        "mma.sync.aligned.m16n8k16.row.col.f32.bf16.bf16.f32 "
        "{%0,%1,%2,%3}, {%4,%5,%6,%7}, {%8,%9}, {%0,%1,%2,%3};"
        : "+f"(d[0]), "+f"(d[1]), "+f"(d[2]), "+f"(d[3])
        : "r"(a[0]), "r"(a[1]), "r"(a[2]), "r"(a[3]), "r"(b[0]), "r"(b[1]));
}

template <int MODE>
__global__ __launch_bounds__(256)
void gemm_mma(const float* __restrict__ A,
              const float* __restrict__ AGG,
              const float* __restrict__ H1,
              const float* __restrict__ epsp,
              const float* __restrict__ W,
              const float* __restrict__ bias,
              float* __restrict__ out,
              int M, int Nout)
{
    __shared__ uint32_t sAhi[TILE_U32];
    __shared__ uint32_t sAlo[TILE_U32];
    __shared__ uint32_t sBhi[TILE_U32];
    __shared__ uint32_t sBlo[TILE_U32];

    const int tid  = threadIdx.x;
    const int wid  = tid >> 5;
    const int lane = tid & 31;
    const int row0 = blockIdx.y * 128;
    const int col0 = blockIdx.x * 128;

    const int warp_m = (wid & 1) * 64;   // 2 warps along m
    const int warp_n = (wid >> 1) * 32;  // 4 warps along n

    float acc[4][4][4];   // [mi][ni][reg]
    #pragma unroll
    for (int mi = 0; mi < 4; mi++)
        #pragma unroll
        for (int ni = 0; ni < 4; ni++)
            #pragma unroll
            for (int r = 0; r < 4; r++) acc[mi][ni][r] = 0.f;

    float eps1 = 0.f;
    if (MODE == MODE_GIN) eps1 = 1.0f + epsp[0];

    #pragma unroll 1
    for (int chunk = 0; chunk < DIM / KC; chunk++) {
        const int kc = chunk * KC;

        // ---- A tile: 128 rows x 32 k (with GIN transform), hi/lo split ----
        #pragma unroll
        for (int i = 0; i < 4; i++) {
            int idx = tid + i * 256;     // 0..1023 float4 slots
            int m  = idx >> 3;           // 0..127
            int kq = idx & 7;            // float4 index within 32 k
            int gm = row0 + m;
            float4 v = make_float4(0.f, 0.f, 0.f, 0.f);
            if (gm < M) {
                v = *((const float4*)(A + (size_t)gm * DIM + kc) + kq);
                if (MODE == MODE_GIN) {
                    float4 g = *((const float4*)(AGG + (size_t)gm * DIM + kc) + kq);
                    v.x = eps1 * v.x + g.x;
                    v.y = eps1 * v.y + g.y;
                    v.z = eps1 * v.z + g.z;
                    v.w = eps1 * v.w + g.w;
                }
            }
            uint32_t h0, l0, h1v, l1v;
            split2(v.x, v.y, h0, l0);
            split2(v.z, v.w, h1v, l1v);
            int o = m * SROW + kq * 2;
            *(uint2*)&sAhi[o] = make_uint2(h0, h1v);
            *(uint2*)&sAlo[o] = make_uint2(l0, l1v);
        }

        // ---- B tile (transposed): Bs[n][k] = W[kc+k][col0+n] ----
        #pragma unroll
        for (int i = 0; i < 4; i++) {
            int idx = tid + i * 256;     // 0..1023: n(128) x kgroup(8)
            int n  = idx & 127;
            int kg = idx >> 7;           // 0..7, 4 consecutive k each
            const float* wp = W + (size_t)(kc + kg * 4) * Nout + col0 + n;
            float w0 = wp[0];
            float w1 = wp[Nout];
            float w2 = wp[2 * (size_t)Nout];
            float w3 = wp[3 * (size_t)Nout];
            uint32_t h0, l0, h1v, l1v;
            split2(w0, w1, h0, l0);
            split2(w2, w3, h1v, l1v);
            int o = n * SROW + kg * 2;
            *(uint2*)&sBhi[o] = make_uint2(h0, h1v);
            *(uint2*)&sBlo[o] = make_uint2(l0, l1v);
        }
        __syncthreads();

        // ---- MMA over this chunk: 2 k16 steps x 3 split terms ----
        #pragma unroll
        for (int s = 0; s < 2; s++) {
            const int cb = s * 8;                 // u32 col base for this k16
            const int lr = lane >> 2;             // 0..7
            const int lc = lane & 3;              // 0..3

            uint32_t Bh[4][2], Bl[4][2];
            #pragma unroll
            for (int ni = 0; ni < 4; ni++) {
                int n = warp_n + ni * 8 + lr;
                int o = n * SROW + cb + lc;
                Bh[ni][0] = sBhi[o];     Bh[ni][1] = sBhi[o + 4];
                Bl[ni][0] = sBlo[o];     Bl[ni][1] = sBlo[o + 4];
            }

            uint32_t Ah[4][4];
            #pragma unroll
            for (int mi = 0; mi < 4; mi++) {
                int m = warp_m + mi * 16 + lr;
                int o = m * SROW + cb + lc;
                Ah[mi][0] = sAhi[o];
                Ah[mi][1] = sAhi[o + 8 * SROW];
                Ah[mi][2] = sAhi[o + 4];
                Ah[mi][3] = sAhi[o + 8 * SROW + 4];
            }
            #pragma unroll
            for (int mi = 0; mi < 4; mi++)
                #pragma unroll
                for (int ni = 0; ni < 4; ni++)
                    mma_bf16(acc[mi][ni], Ah[mi], Bh[ni]);
            #pragma unroll
            for (int mi = 0; mi < 4; mi++)
                #pragma unroll
                for (int ni = 0; ni < 4; ni++)
                    mma_bf16(acc[mi][ni], Ah[mi], Bl[ni]);

            uint32_t Al[4][4];
            #pragma unroll
            for (int mi = 0; mi < 4; mi++) {
                int m = warp_m + mi * 16 + lr;
                int o = m * SROW + cb + lc;
                Al[mi][0] = sAlo[o];
                Al[mi][1] = sAlo[o + 8 * SROW];
                Al[mi][2] = sAlo[o + 4];
                Al[mi][3] = sAlo[o + 8 * SROW + 4];
            }
            #pragma unroll
            for (int mi = 0; mi < 4; mi++)
                #pragma unroll
                for (int ni = 0; ni < 4; ni++)
                    mma_bf16(acc[mi][ni], Al[mi], Bh[ni]);
        }
        __syncthreads();
    }

    // ---- epilogue ----
    const int lr = lane >> 2;
    const int lc = lane & 3;
    #pragma unroll
    for (int mi = 0; mi < 4; mi++) {
        #pragma unroll
        for (int half = 0; half < 2; half++) {
            int gm = row0 + warp_m + mi * 16 + half * 8 + lr;
            if (gm >= M) continue;
            #pragma unroll
            for (int ni = 0; ni < 4; ni++) {
                int gn = col0 + warp_n + ni * 8 + lc * 2;
                float2 r;
                r.x = acc[mi][ni][half * 2 + 0];
                r.y = acc[mi][ni][half * 2 + 1];
                float2 bb = *(const float2*)(bias + gn);
                r.x += bb.x; r.y += bb.y;
                if (MODE == MODE_GIN || MODE == MODE_RES || MODE == MODE_RES_POOL) {
                    r.x = fmaxf(r.x, 0.f);
                    r.y = fmaxf(r.y, 0.f);
                }
                if (MODE == MODE_RES) {
                    float2 a1 = *(const float2*)(A + (size_t)gm * DIM + gn);
                    r.x += a1.x; r.y += a1.y;
                }
                if (MODE == MODE_RES_POOL) {
                    float2 a2 = *(const float2*)(A + (size_t)gm * DIM + gn);
                    float2 h1 = *(const float2*)(H1 + (size_t)gm * DIM + gn);
                    r.x = 0.5f * (r.x + a2.x + h1.x);
                    r.y = 0.5f * (r.y + a2.y + h1.y);
                }
                *(float2*)(out + (size_t)gm * Nout + gn) = r;
            }
        }
    }
}

// ---------------- launch ----------------
extern "C" void kernel_launch(void* const* d_in, const int* in_sizes, int n_in,
                              void* d_out, int out_size)
{
    const float* X    = (const float*)d_in[0];
    const void*  src  = d_in[1];
    const void*  dst  = d_in[2];
    const float* eps1 = (const float*)d_in[3];
    const float* W1   = (const float*)d_in[4];
    const float* b1   = (const float*)d_in[5];
    const float* rW1  = (const float*)d_in[6];
    const float* rb1  = (const float*)d_in[7];
    const float* eps2 = (const float*)d_in[8];
    const float* W2   = (const float*)d_in[9];
    const float* b2   = (const float*)d_in[10];
    const float* rW2  = (const float*)d_in[11];
    const float* rb2  = (const float*)d_in[12];
    const float* linW = (const float*)d_in[13];
    const float* linb = (const float*)d_in[14];
    float* out = (float*)d_out;

    const int M  = in_sizes[0] / DIM;   // 100000
    const int nE = in_sizes[1];         // 1600000

    float4 *agg4, *abuf4, *h14, *pool4;
    cudaGetSymbolAddress((void**)&agg4,  g_agg);
    cudaGetSymbolAddress((void**)&abuf4, g_abuf);
    cudaGetSymbolAddress((void**)&h14,   g_h1);
    cudaGetSymbolAddress((void**)&pool4, g_pool);
    float* agg  = (float*)agg4;
    float* abuf = (float*)abuf4;
    float* h1   = (float*)h14;
    float* pool = (float*)pool4;

    const int n4 = M * (DIM / 4);
    const int zeroBlocks = 1024;
    const int scatterBlocks = (int)(((long long)nE * 32 + 255) / 256);

    const int mBlocks = (M + 127) / 128;
    dim3 g128(1, mBlocks);
    dim3 gfin(NUM_LABELS / 128, mBlocks);

    detect_kernel<<<1, 32>>>((const unsigned long long*)src);

    // ---- layer 1 ----
    zero_kernel<<<zeroBlocks, 256>>>(agg4, n4);
    scatter_kernel<<<scatterBlocks, 256>>>((const float4*)X, src, dst, agg, nE);
    gemm_mma<MODE_GIN><<<g128, 256>>>(X, agg, nullptr, eps1, W1, b1, abuf, M, DIM);
    gemm_mma<MODE_RES><<<g128, 256>>>(abuf, nullptr, nullptr, nullptr, rW1, rb1, h1, M, DIM);

    // ---- layer 2 ----
    zero_kernel<<<zeroBlocks, 256>>>(agg4, n4);
    scatter_kernel<<<scatterBlocks, 256>>>((const float4*)h1, src, dst, agg, nE);
    gemm_mma<MODE_GIN><<<g128, 256>>>(h1, agg, nullptr, eps2, W2, b2, abuf, M, DIM);
    gemm_mma<MODE_RES_POOL><<<g128, 256>>>(abuf, nullptr, h1, nullptr, rW2, rb2, pool, M, DIM);

    // ---- head ----
    gemm_mma<MODE_FINAL><<<gfin, 256>>>(pool, nullptr, nullptr, nullptr, linW, linb, out, M, NUM_LABELS);
}

// round 5
// speedup vs baseline: 1.5077x; 1.5077x over previous
#include <cuda_runtime.h>
#include <cuda_bf16.h>
#include <cstdint>

#define N_NODES 100000
#define NPAD    100096
#define DIM 128
#define NUM_LABELS 1024

// ---------------- scratch (no allocations allowed) ----------------
__device__ float4   g_agg [ (size_t)N_NODES * (DIM/4) ];
__device__ float4   g_abuf[ (size_t)N_NODES * (DIM/4) ];
__device__ float4   g_h1  [ (size_t)N_NODES * (DIM/4) ];
__device__ uint32_t g_abuf_h[(size_t)NPAD * 64];
__device__ uint32_t g_abuf_l[(size_t)NPAD * 64];
__device__ uint32_t g_pool_h[(size_t)NPAD * 64];
__device__ uint32_t g_pool_l[(size_t)NPAD * 64];
// pre-split transposed weights: 4 x [4 chunks][128 n][16 u32] + lin [4][1024][16]
#define OFF_W1  0
#define OFF_RW1 8192
#define OFF_W2  16384
#define OFF_RW2 24576
#define OFF_LIN 32768
__device__ uint32_t g_wb_h[98304];
__device__ uint32_t g_wb_l[98304];
__device__ int      g_idx64;

// ---------------- helpers ----------------
__device__ __forceinline__ uint32_t smem_to_u32(const void* p) {
    uint32_t a;
    asm("{ .reg .u64 t; cvta.to.shared.u64 t, %1; cvt.u32.u64 %0, t; }" : "=r"(a) : "l"(p));
    return a;
}
// split x,y (consecutive k) into bf16 hi/lo packed: lo16 = x, hi16 = y
__device__ __forceinline__ void split2(float x, float y, uint32_t& hi, uint32_t& lo) {
    __nv_bfloat16 hx = __float2bfloat16(x);
    __nv_bfloat16 hy = __float2bfloat16(y);
    __nv_bfloat16 lx = __float2bfloat16(x - __bfloat162float(hx));
    __nv_bfloat16 ly = __float2bfloat16(y - __bfloat162float(hy));
    hi = ((uint32_t)__bfloat16_as_ushort(hy) << 16) | (uint32_t)__bfloat16_as_ushort(hx);
    lo = ((uint32_t)__bfloat16_as_ushort(ly) << 16) | (uint32_t)__bfloat16_as_ushort(lx);
}
__device__ __forceinline__ void mma_bf16(float* d, const uint32_t* a, const uint32_t* b) {
    asm volatile(
        "mma.sync.aligned.m16n8k16.row.col.f32.bf16.bf16.f32 "
        "{%0,%1,%2,%3}, {%4,%5,%6,%7}, {%8,%9}, {%0,%1,%2,%3};"
        : "+f"(d[0]), "+f"(d[1]), "+f"(d[2]), "+f"(d[3])
        : "r"(a[0]), "r"(a[1]), "r"(a[2]), "r"(a[3]), "r"(b[0]), "r"(b[1]));
}
#define CPA16(dst, src) \
    asm volatile("cp.async.ca.shared.global [%0], [%1], 16;" :: "r"(dst), "l"(src) : "memory")

// ---------------- index-width detection ----------------
__global__ void detect_kernel(const unsigned long long* __restrict__ src) {
    if (threadIdx.x == 0 && blockIdx.x == 0) {
        int is64 = 1;
        for (int i = 0; i < 64; i++) {
            if (src[i] >> 32) { is64 = 0; break; }
        }
        g_idx64 = is64;
    }
}

// ---------------- weight pre-split: Wt[n][k] hi/lo, chunk-major ----------------
// out[(chunk*Nout + n)*16 + j] packs k = 2*(chunk*16+j), 2*(chunk*16+j)+1
__global__ void split_w_kernel(const float* __restrict__ W,
                               uint32_t* __restrict__ hi, uint32_t* __restrict__ lo,
                               int Nout)
{
    int t = blockIdx.x * blockDim.x + threadIdx.x;
    if (t >= Nout * 64) return;
    int n = t % Nout;
    int p = t / Nout;              // u32 col 0..63
    float x = W[(size_t)(2 * p)     * Nout + n];
    float y = W[(size_t)(2 * p + 1) * Nout + n];
    uint32_t h, l;
    split2(x, y, h, l);
    int chunk = p >> 4, j = p & 15;
    hi[((size_t)chunk * Nout + n) * 16 + j] = h;
    lo[((size_t)chunk * Nout + n) * 16 + j] = l;
}

// ---------------- zero kernel ----------------
__global__ void zero_kernel(float4* __restrict__ p, int n4) {
    int i = blockIdx.x * blockDim.x + threadIdx.x;
    int stride = gridDim.x * blockDim.x;
    float4 z = make_float4(0.f, 0.f, 0.f, 0.f);
    for (; i < n4; i += stride) p[i] = z;
}

// ---------------- scatter-add: one warp per edge ----------------
__global__ void scatter_kernel(const float4* __restrict__ h,
                               const void* __restrict__ srcv,
                               const void* __restrict__ dstv,
                               float* __restrict__ agg, int nE)
{
    int w = (blockIdx.x * blockDim.x + threadIdx.x) >> 5;
    int lane = threadIdx.x & 31;
    if (w >= nE) return;
    long long s, d;
    if (g_idx64) {
        s = ((const long long*)srcv)[w];
        d = ((const long long*)dstv)[w];
    } else {
        s = ((const int*)srcv)[w];
        d = ((const int*)dstv)[w];
    }
    float4 v = h[(size_t)s * 32 + lane];
    float* p = agg + (size_t)d * 128 + lane * 4;
    asm volatile("red.global.add.v4.f32 [%0], {%1,%2,%3,%4};"
                 :: "l"(p), "f"(v.x), "f"(v.y), "f"(v.z), "f"(v.w) : "memory");
}

// ======================= mma.sync bf16-split fused GEMM =======================
#define MODE_GIN 0
#define MODE_RES 1
#define MODE_RES_POOL 2
#define MODE_FINAL 3

#define SROW 20               // row stride in u32 (16 data + 4 pad)
#define TILE_U32 (128 * SROW) // 2560 u32 = 10240 B per tile
#define SM_GIN  (4 * TILE_U32 * 4)       // 40960 B (single stage)
#define SM_PIPE (2 * 4 * TILE_U32 * 4)   // 81920 B (double buffered)

template <int MODE>
__global__ __launch_bounds__(256)
void gemm_mma(const float* __restrict__ A,        // fp32 A (GIN mainloop / RES(_POOL) epilogue)
              const uint32_t* __restrict__ Ah,    // pre-split A hi (non-GIN)
              const uint32_t* __restrict__ Al,
              const float* __restrict__ AGG,
              const float* __restrict__ H1,
              const float* __restrict__ epsp,
              const uint32_t* __restrict__ Bh,    // pre-split W^T hi
              const uint32_t* __restrict__ Bl,
              const float* __restrict__ bias,
              float* __restrict__ out,            // fp32 out (GIN/RES/FINAL)
              uint32_t* __restrict__ outh,        // split out (GIN/RES_POOL)
              uint32_t* __restrict__ outl,
              int M, int Nout)
{
    extern __shared__ uint32_t smem_u[];
    constexpr bool APRE = (MODE != MODE_GIN);

    const int tid  = threadIdx.x;
    const int wid  = tid >> 5;
    const int lane = tid & 31;
    const int row0 = blockIdx.y * 128;
    const int col0 = blockIdx.x * 128;
    const int warp_m = (wid & 1) * 64;
    const int warp_n = (wid >> 1) * 32;
    const uint32_t sbase = smem_to_u32(smem_u);

    float acc[4][4][4];
    #pragma unroll
    for (int mi = 0; mi < 4; mi++)
        #pragma unroll
        for (int ni = 0; ni < 4; ni++)
            #pragma unroll
            for (int r = 0; r < 4; r++) acc[mi][ni][r] = 0.f;

    float eps1 = 0.f;
    if (MODE == MODE_GIN) eps1 = 1.0f + epsp[0];

    // cp.async issue of one chunk into one stage (pre-split path)
    auto issue = [&](int c, int stage) {
        #pragma unroll
        for (int i = 0; i < 8; i++) {
            int idx  = tid + i * 256;   // 0..2047
            int tile = idx >> 9;        // 0 Ahi, 1 Alo, 2 Bhi, 3 Blo
            int r    = idx & 511;
            int row  = r >> 2;
            int j4   = r & 3;
            const uint32_t* g;
            if (tile == 0)      g = Ah + (size_t)(row0 + row) * 64 + c * 16 + j4 * 4;
            else if (tile == 1) g = Al + (size_t)(row0 + row) * 64 + c * 16 + j4 * 4;
            else if (tile == 2) g = Bh + ((size_t)c * Nout + col0 + row) * 16 + j4 * 4;
            else                g = Bl + ((size_t)c * Nout + col0 + row) * 16 + j4 * 4;
            uint32_t d = sbase + (uint32_t)(stage * 4 * TILE_U32 + tile * TILE_U32 + row * SROW + j4 * 4) * 4;
            CPA16(d, g);
        }
        asm volatile("cp.async.commit_group;" ::: "memory");
    };

    if (APRE) issue(0, 0);

    #pragma unroll 1
    for (int c = 0; c < DIM / 32; c++) {
        const int stage = APRE ? (c & 1) : 0;
        uint32_t* sA_hi = smem_u + stage * 4 * TILE_U32;
        uint32_t* sA_lo = sA_hi + TILE_U32;
        uint32_t* sB_hi = sA_hi + 2 * TILE_U32;
        uint32_t* sB_lo = sA_hi + 3 * TILE_U32;

        if (APRE) {
            if (c + 1 < DIM / 32) {
                issue(c + 1, (c + 1) & 1);
                asm volatile("cp.async.wait_group 1;" ::: "memory");
            } else {
                asm volatile("cp.async.wait_group 0;" ::: "memory");
            }
        } else {
            const int kc = c * 32;
            // A tile: fp32 load + GIN transform + split
            #pragma unroll
            for (int i = 0; i < 4; i++) {
                int idx = tid + i * 256;
                int m  = idx >> 3;
                int kq = idx & 7;
                int gm = row0 + m;
                float4 v = make_float4(0.f, 0.f, 0.f, 0.f);
                if (gm < M) {
                    v = *((const float4*)(A + (size_t)gm * DIM + kc) + kq);
                    float4 g = *((const float4*)(AGG + (size_t)gm * DIM + kc) + kq);
                    v.x = eps1 * v.x + g.x;
                    v.y = eps1 * v.y + g.y;
                    v.z = eps1 * v.z + g.z;
                    v.w = eps1 * v.w + g.w;
                }
                uint32_t h0, l0, h1v, l1v;
                split2(v.x, v.y, h0, l0);
                split2(v.z, v.w, h1v, l1v);
                int o = m * SROW + kq * 2;
                *(uint2*)&sA_hi[o] = make_uint2(h0, h1v);
                *(uint2*)&sA_lo[o] = make_uint2(l0, l1v);
            }
            // B tile: pre-split vector copy
            #pragma unroll
            for (int i = 0; i < 4; i++) {
                int idx  = tid + i * 256;   // 0..1023
                int tile = idx >> 9;        // 0 hi, 1 lo
                int r    = idx & 511;
                int n    = r >> 2;
                int j4   = r & 3;
                const uint32_t* g = (tile ? Bl : Bh) + ((size_t)c * Nout + col0 + n) * 16 + j4 * 4;
                uint4 v4 = *(const uint4*)g;
                uint32_t* s = tile ? sB_lo : sB_hi;
                *(uint4*)&s[n * SROW + j4 * 4] = v4;
            }
        }
        __syncthreads();

        // ---- MMA: 2 k16 steps x 3 split terms ----
        #pragma unroll
        for (int s = 0; s < 2; s++) {
            const int cb = s * 8;
            const int lr = lane >> 2;
            const int lc = lane & 3;

            uint32_t Bfh[4][2], Bfl[4][2];
            #pragma unroll
            for (int ni = 0; ni < 4; ni++) {
                int n = warp_n + ni * 8 + lr;
                int o = n * SROW + cb + lc;
                Bfh[ni][0] = sB_hi[o];  Bfh[ni][1] = sB_hi[o + 4];
                Bfl[ni][0] = sB_lo[o];  Bfl[ni][1] = sB_lo[o + 4];
            }
            uint32_t Afh[4][4];
            #pragma unroll
            for (int mi = 0; mi < 4; mi++) {
                int m = warp_m + mi * 16 + lr;
                int o = m * SROW + cb + lc;
                Afh[mi][0] = sA_hi[o];
                Afh[mi][1] = sA_hi[o + 8 * SROW];
                Afh[mi][2] = sA_hi[o + 4];
                Afh[mi][3] = sA_hi[o + 8 * SROW + 4];
            }
            #pragma unroll
            for (int mi = 0; mi < 4; mi++)
                #pragma unroll
                for (int ni = 0; ni < 4; ni++)
                    mma_bf16(acc[mi][ni], Afh[mi], Bfh[ni]);
            #pragma unroll
            for (int mi = 0; mi < 4; mi++)
                #pragma unroll
                for (int ni = 0; ni < 4; ni++)
                    mma_bf16(acc[mi][ni], Afh[mi], Bfl[ni]);

            uint32_t Afl[4][4];
            #pragma unroll
            for (int mi = 0; mi < 4; mi++) {
                int m = warp_m + mi * 16 + lr;
                int o = m * SROW + cb + lc;
                Afl[mi][0] = sA_lo[o];
                Afl[mi][1] = sA_lo[o + 8 * SROW];
                Afl[mi][2] = sA_lo[o + 4];
                Afl[mi][3] = sA_lo[o + 8 * SROW + 4];
            }
            #pragma unroll
            for (int mi = 0; mi < 4; mi++)
                #pragma unroll
                for (int ni = 0; ni < 4; ni++)
                    mma_bf16(acc[mi][ni], Afl[mi], Bfh[ni]);
        }
        __syncthreads();
    }

    // ---- epilogue ----
    const int lr = lane >> 2;
    const int lc = lane & 3;
    #pragma unroll
    for (int mi = 0; mi < 4; mi++) {
        #pragma unroll
        for (int half = 0; half < 2; half++) {
            int gm = row0 + warp_m + mi * 16 + half * 8 + lr;
            if (gm >= M) continue;
            #pragma unroll
            for (int ni = 0; ni < 4; ni++) {
                int gn = col0 + warp_n + ni * 8 + lc * 2;
                float2 r;
                r.x = acc[mi][ni][half * 2 + 0];
                r.y = acc[mi][ni][half * 2 + 1];
                float2 bb = *(const float2*)(bias + gn);
                r.x += bb.x; r.y += bb.y;
                if (MODE != MODE_FINAL) {
                    r.x = fmaxf(r.x, 0.f);
                    r.y = fmaxf(r.y, 0.f);
                }
                if (MODE == MODE_RES) {
                    float2 a1 = *(const float2*)(A + (size_t)gm * DIM + gn);
                    r.x += a1.x; r.y += a1.y;
                }
                if (MODE == MODE_RES_POOL) {
                    float2 a2 = *(const float2*)(A + (size_t)gm * DIM + gn);
                    float2 hh = *(const float2*)(H1 + (size_t)gm * DIM + gn);
                    r.x = 0.5f * (r.x + a2.x + hh.x);
                    r.y = 0.5f * (r.y + a2.y + hh.y);
                }
                if (MODE == MODE_GIN || MODE == MODE_RES || MODE == MODE_FINAL)
                    *(float2*)(out + (size_t)gm * Nout + gn) = r;
                if (MODE == MODE_GIN || MODE == MODE_RES_POOL) {
                    uint32_t h, l;
                    split2(r.x, r.y, h, l);
                    size_t oidx = (size_t)gm * (Nout >> 1) + (gn >> 1);
                    outh[oidx] = h;
                    outl[oidx] = l;
                }
            }
        }
    }
}

// ---------------- launch ----------------
extern "C" void kernel_launch(void* const* d_in, const int* in_sizes, int n_in,
                              void* d_out, int out_size)
{
    const float* X    = (const float*)d_in[0];
    const void*  src  = d_in[1];
    const void*  dst  = d_in[2];
    const float* eps1 = (const float*)d_in[3];
    const float* W1   = (const float*)d_in[4];
    const float* b1   = (const float*)d_in[5];
    const float* rW1  = (const float*)d_in[6];
    const float* rb1  = (const float*)d_in[7];
    const float* eps2 = (const float*)d_in[8];
    const float* W2   = (const float*)d_in[9];
    const float* b2   = (const float*)d_in[10];
    const float* rW2  = (const float*)d_in[11];
    const float* rb2  = (const float*)d_in[12];
    const float* linW = (const float*)d_in[13];
    const float* linb = (const float*)d_in[14];
    float* out = (float*)d_out;

    const int M  = in_sizes[0] / DIM;   // 100000
    const int nE = in_sizes[1];         // 1600000

    float4 *agg4, *abuf4, *h14;
    uint32_t *abh, *abl, *plh, *pll, *wbh, *wbl;
    cudaGetSymbolAddress((void**)&agg4,  g_agg);
    cudaGetSymbolAddress((void**)&abuf4, g_abuf);
    cudaGetSymbolAddress((void**)&h14,   g_h1);
    cudaGetSymbolAddress((void**)&abh,   g_abuf_h);
    cudaGetSymbolAddress((void**)&abl,   g_abuf_l);
    cudaGetSymbolAddress((void**)&plh,   g_pool_h);
    cudaGetSymbolAddress((void**)&pll,   g_pool_l);
    cudaGetSymbolAddress((void**)&wbh,   g_wb_h);
    cudaGetSymbolAddress((void**)&wbl,   g_wb_l);
    float* agg  = (float*)agg4;
    float* abuf = (float*)abuf4;
    float* h1   = (float*)h14;

    cudaFuncSetAttribute(gemm_mma<MODE_RES>,      cudaFuncAttributeMaxDynamicSharedMemorySize, SM_PIPE);
    cudaFuncSetAttribute(gemm_mma<MODE_RES_POOL>, cudaFuncAttributeMaxDynamicSharedMemorySize, SM_PIPE);
    cudaFuncSetAttribute(gemm_mma<MODE_FINAL>,    cudaFuncAttributeMaxDynamicSharedMemorySize, SM_PIPE);

    const int n4 = M * (DIM / 4);
    const int zeroBlocks = 1024;
    const int scatterBlocks = (int)(((long long)nE * 32 + 255) / 256);
    const int mBlocks = (M + 127) / 128;
    dim3 g128(1, mBlocks);
    dim3 gfin(NUM_LABELS / 128, mBlocks);

    detect_kernel<<<1, 32>>>((const unsigned long long*)src);

    // weight pre-splits
    split_w_kernel<<<(128 * 64 + 255) / 256, 256>>>(W1,   wbh + OFF_W1,  wbl + OFF_W1,  128);
    split_w_kernel<<<(128 * 64 + 255) / 256, 256>>>(rW1,  wbh + OFF_RW1, wbl + OFF_RW1, 128);
    split_w_kernel<<<(128 * 64 + 255) / 256, 256>>>(W2,   wbh + OFF_W2,  wbl + OFF_W2,  128);
    split_w_kernel<<<(128 * 64 + 255) / 256, 256>>>(rW2,  wbh + OFF_RW2, wbl + OFF_RW2, 128);
    split_w_kernel<<<(1024 * 64 + 255) / 256, 256>>>(linW, wbh + OFF_LIN, wbl + OFF_LIN, 1024);

    // ---- layer 1 ----
    zero_kernel<<<zeroBlocks, 256>>>(agg4, n4);
    scatter_kernel<<<scatterBlocks, 256>>>((const float4*)X, src, dst, agg, nE);
    gemm_mma<MODE_GIN><<<g128, 256, SM_GIN>>>(X, nullptr, nullptr, agg, nullptr, eps1,
                                              wbh + OFF_W1, wbl + OFF_W1, b1,
                                              abuf, abh, abl, M, DIM);
    gemm_mma<MODE_RES><<<g128, 256, SM_PIPE>>>(abuf, abh, abl, nullptr, nullptr, nullptr,
                                               wbh + OFF_RW1, wbl + OFF_RW1, rb1,
                                               h1, nullptr, nullptr, M, DIM);

    // ---- layer 2 ----
    zero_kernel<<<zeroBlocks, 256>>>(agg4, n4);
    scatter_kernel<<<scatterBlocks, 256>>>((const float4*)h1, src, dst, agg, nE);
    gemm_mma<MODE_GIN><<<g128, 256, SM_GIN>>>(h1, nullptr, nullptr, agg, nullptr, eps2,
                                              wbh + OFF_W2, wbl + OFF_W2, b2,
                                              abuf, abh, abl, M, DIM);
    gemm_mma<MODE_RES_POOL><<<g128, 256, SM_PIPE>>>(abuf, abh, abl, nullptr, h1, nullptr,
                                                    wbh + OFF_RW2, wbl + OFF_RW2, rb2,
                                                    nullptr, plh, pll, M, DIM);

    // ---- head ----
    gemm_mma<MODE_FINAL><<<gfin, 256, SM_PIPE>>>(nullptr, plh, pll, nullptr, nullptr, nullptr,
                                                 wbh + OFF_LIN, wbl + OFF_LIN, linb,
                                                 out, nullptr, nullptr, M, NUM_LABELS);
}

// round 6
// speedup vs baseline: 1.8309x; 1.2144x over previous
#include <cuda_runtime.h>
#include <cuda_bf16.h>
#include <cstdint>

#define N_NODES 100000
#define NPAD    100096
#define DIM 128
#define NUM_LABELS 1024
#define MAX_E 1700000

// ---------------- scratch (no allocations allowed) ----------------
__device__ float4   g_abuf[ (size_t)N_NODES * (DIM/4) ];
__device__ float4   g_h1  [ (size_t)N_NODES * (DIM/4) ];
__device__ uint32_t g_gin_h [(size_t)NPAD * 64];   // pre-split GIN GEMM input
__device__ uint32_t g_gin_l [(size_t)NPAD * 64];
__device__ uint32_t g_abuf_h[(size_t)NPAD * 64];
__device__ uint32_t g_abuf_l[(size_t)NPAD * 64];
__device__ uint32_t g_pool_h[(size_t)NPAD * 64];
__device__ uint32_t g_pool_l[(size_t)NPAD * 64];
// CSR by dst
__device__ int g_deg   [NPAD];
__device__ int g_rowptr[NPAD + 1];
__device__ int g_cursor[NPAD];
__device__ int g_csrsrc[MAX_E];
// pre-split transposed weights
#define OFF_W1  0
#define OFF_RW1 8192
#define OFF_W2  16384
#define OFF_RW2 24576
#define OFF_LIN 32768
__device__ uint32_t g_wb_h[98304];
__device__ uint32_t g_wb_l[98304];
__device__ int      g_idx64;

// ---------------- helpers ----------------
__device__ __forceinline__ uint32_t smem_to_u32(const void* p) {
    uint32_t a;
    asm("{ .reg .u64 t; cvta.to.shared.u64 t, %1; cvt.u32.u64 %0, t; }" : "=r"(a) : "l"(p));
    return a;
}
__device__ __forceinline__ void split2(float x, float y, uint32_t& hi, uint32_t& lo) {
    __nv_bfloat16 hx = __float2bfloat16(x);
    __nv_bfloat16 hy = __float2bfloat16(y);
    __nv_bfloat16 lx = __float2bfloat16(x - __bfloat162float(hx));
    __nv_bfloat16 ly = __float2bfloat16(y - __bfloat162float(hy));
    hi = ((uint32_t)__bfloat16_as_ushort(hy) << 16) | (uint32_t)__bfloat16_as_ushort(hx);
    lo = ((uint32_t)__bfloat16_as_ushort(ly) << 16) | (uint32_t)__bfloat16_as_ushort(lx);
}
__device__ __forceinline__ void mma_bf16(float* d, const uint32_t* a, const uint32_t* b) {
    asm volatile(
        "mma.sync.aligned.m16n8k16.row.col.f32.bf16.bf16.f32 "
        "{%0,%1,%2,%3}, {%4,%5,%6,%7}, {%8,%9}, {%0,%1,%2,%3};"
        : "+f"(d[0]), "+f"(d[1]), "+f"(d[2]), "+f"(d[3])
        : "r"(a[0]), "r"(a[1]), "r"(a[2]), "r"(a[3]), "r"(b[0]), "r"(b[1]));
}
#define CPA16(dst, src) \
    asm volatile("cp.async.ca.shared.global [%0], [%1], 16;" :: "r"(dst), "l"(src) : "memory")

__device__ __forceinline__ long long edge_idx(const void* p, int i) {
    return g_idx64 ? ((const long long*)p)[i] : (long long)((const int*)p)[i];
}

// ---------------- index-width detection ----------------
__global__ void detect_kernel(const unsigned long long* __restrict__ src) {
    if (threadIdx.x == 0 && blockIdx.x == 0) {
        int is64 = 1;
        for (int i = 0; i < 64; i++) {
            if (src[i] >> 32) { is64 = 0; break; }
        }
        g_idx64 = is64;
    }
}

// ---------------- CSR build ----------------
__global__ void zero_deg_kernel(int n) {
    int i = blockIdx.x * blockDim.x + threadIdx.x;
    if (i < n) g_deg[i] = 0;
}
__global__ void hist_kernel(const void* __restrict__ dstv, int nE) {
    int i = blockIdx.x * blockDim.x + threadIdx.x;
    int stride = gridDim.x * blockDim.x;
    for (; i < nE; i += stride) {
        int d = (int)edge_idx(dstv, i);
        atomicAdd(&g_deg[d], 1);
    }
}
__global__ __launch_bounds__(1024) void scan_kernel(int n) {
    __shared__ int ssum[1024];
    int t = threadIdx.x;
    int chunk = (n + 1023) / 1024;
    int b = t * chunk;
    int e = min(b + chunk, n);
    int s = 0;
    for (int i = b; i < e; i++) s += g_deg[i];
    ssum[t] = s;
    __syncthreads();
    // Hillis-Steele inclusive scan
    for (int off = 1; off < 1024; off <<= 1) {
        int v = (t >= off) ? ssum[t - off] : 0;
        __syncthreads();
        ssum[t] += v;
        __syncthreads();
    }
    int ex = (t == 0) ? 0 : ssum[t - 1];
    for (int i = b; i < e; i++) {
        g_rowptr[i] = ex;
        g_cursor[i] = ex;
        ex += g_deg[i];
    }
    if (t == 0) g_rowptr[n] = ssum[1023];
}
__global__ void fill_kernel(const void* __restrict__ srcv,
                            const void* __restrict__ dstv, int nE) {
    int i = blockIdx.x * blockDim.x + threadIdx.x;
    int stride = gridDim.x * blockDim.x;
    for (; i < nE; i += stride) {
        int d = (int)edge_idx(dstv, i);
        int s = (int)edge_idx(srcv, i);
        int pos = atomicAdd(&g_cursor[d], 1);
        g_csrsrc[pos] = s;
    }
}

// ---------------- aggregation: one warp per node ----------------
// acc = (1+eps)*h[node] + sum_{s in neighbors(node)} h[s];  write hi/lo split
__global__ void agg_kernel(const float4* __restrict__ h,
                           const float* __restrict__ epsp,
                           uint32_t* __restrict__ outh,
                           uint32_t* __restrict__ outl,
                           int M)
{
    int node = (blockIdx.x * blockDim.x + threadIdx.x) >> 5;
    int lane = threadIdx.x & 31;
    if (node >= M) return;
    const float eps1 = 1.0f + epsp[0];

    float4 acc = h[(size_t)node * 32 + lane];
    acc.x *= eps1; acc.y *= eps1; acc.z *= eps1; acc.w *= eps1;

    int e   = g_rowptr[node];
    int end = g_rowptr[node + 1];
    // unroll-by-4 for MLP
    for (; e + 4 <= end; e += 4) {
        int s0 = g_csrsrc[e], s1 = g_csrsrc[e + 1], s2 = g_csrsrc[e + 2], s3 = g_csrsrc[e + 3];
        float4 v0 = h[(size_t)s0 * 32 + lane];
        float4 v1 = h[(size_t)s1 * 32 + lane];
        float4 v2 = h[(size_t)s2 * 32 + lane];
        float4 v3 = h[(size_t)s3 * 32 + lane];
        acc.x += v0.x + v1.x + v2.x + v3.x;
        acc.y += v0.y + v1.y + v2.y + v3.y;
        acc.z += v0.z + v1.z + v2.z + v3.z;
        acc.w += v0.w + v1.w + v2.w + v3.w;
    }
    for (; e < end; e++) {
        int s = g_csrsrc[e];
        float4 v = h[(size_t)s * 32 + lane];
        acc.x += v.x; acc.y += v.y; acc.z += v.z; acc.w += v.w;
    }

    uint32_t h0, l0, h1v, l1v;
    split2(acc.x, acc.y, h0, l0);
    split2(acc.z, acc.w, h1v, l1v);
    size_t o = (size_t)node * 64 + lane * 2;
    *(uint2*)&outh[o] = make_uint2(h0, h1v);
    *(uint2*)&outl[o] = make_uint2(l0, l1v);
}

// ---------------- weight pre-split ----------------
__global__ void split_w_kernel(const float* __restrict__ W,
                               uint32_t* __restrict__ hi, uint32_t* __restrict__ lo,
                               int Nout)
{
    int t = blockIdx.x * blockDim.x + threadIdx.x;
    if (t >= Nout * 64) return;
    int n = t % Nout;
    int p = t / Nout;
    float x = W[(size_t)(2 * p)     * Nout + n];
    float y = W[(size_t)(2 * p + 1) * Nout + n];
    uint32_t h, l;
    split2(x, y, h, l);
    int chunk = p >> 4, j = p & 15;
    hi[((size_t)chunk * Nout + n) * 16 + j] = h;
    lo[((size_t)chunk * Nout + n) * 16 + j] = l;
}

// ======================= mma.sync bf16-split fused GEMM (all pre-split) =======
#define MODE_GIN 0
#define MODE_RES 1
#define MODE_RES_POOL 2
#define MODE_FINAL 3

#define SROW 20
#define TILE_U32 (128 * SROW)
#define SM_PIPE (2 * 4 * TILE_U32 * 4)   // 81920 B

template <int MODE>
__global__ __launch_bounds__(256)
void gemm_mma(const float* __restrict__ A,        // fp32 for epilogue (RES/RES_POOL)
              const uint32_t* __restrict__ Ah,
              const uint32_t* __restrict__ Al,
              const float* __restrict__ H1,
              const uint32_t* __restrict__ Bh,
              const uint32_t* __restrict__ Bl,
              const float* __restrict__ bias,
              float* __restrict__ out,
              uint32_t* __restrict__ outh,
              uint32_t* __restrict__ outl,
              int M, int Nout)
{
    extern __shared__ uint32_t smem_u[];

    const int tid  = threadIdx.x;
    const int wid  = tid >> 5;
    const int lane = tid & 31;
    const int row0 = blockIdx.y * 128;
    const int col0 = blockIdx.x * 128;
    const int warp_m = (wid & 1) * 64;
    const int warp_n = (wid >> 1) * 32;
    const uint32_t sbase = smem_to_u32(smem_u);

    float acc[4][4][4];
    #pragma unroll
    for (int mi = 0; mi < 4; mi++)
        #pragma unroll
        for (int ni = 0; ni < 4; ni++)
            #pragma unroll
            for (int r = 0; r < 4; r++) acc[mi][ni][r] = 0.f;

    auto issue = [&](int c, int stage) {
        #pragma unroll
        for (int i = 0; i < 8; i++) {
            int idx  = tid + i * 256;
            int tile = idx >> 9;
            int r    = idx & 511;
            int row  = r >> 2;
            int j4   = r & 3;
            const uint32_t* g;
            if (tile == 0)      g = Ah + (size_t)(row0 + row) * 64 + c * 16 + j4 * 4;
            else if (tile == 1) g = Al + (size_t)(row0 + row) * 64 + c * 16 + j4 * 4;
            else if (tile == 2) g = Bh + ((size_t)c * Nout + col0 + row) * 16 + j4 * 4;
            else                g = Bl + ((size_t)c * Nout + col0 + row) * 16 + j4 * 4;
            uint32_t d = sbase + (uint32_t)(stage * 4 * TILE_U32 + tile * TILE_U32 + row * SROW + j4 * 4) * 4;
            CPA16(d, g);
        }
        asm volatile("cp.async.commit_group;" ::: "memory");
    };

    issue(0, 0);

    #pragma unroll 1
    for (int c = 0; c < DIM / 32; c++) {
        const int stage = c & 1;
        uint32_t* sA_hi = smem_u + stage * 4 * TILE_U32;
        uint32_t* sA_lo = sA_hi + TILE_U32;
        uint32_t* sB_hi = sA_hi + 2 * TILE_U32;
        uint32_t* sB_lo = sA_hi + 3 * TILE_U32;

        if (c + 1 < DIM / 32) {
            issue(c + 1, (c + 1) & 1);
            asm volatile("cp.async.wait_group 1;" ::: "memory");
        } else {
            asm volatile("cp.async.wait_group 0;" ::: "memory");
        }
        __syncthreads();

        #pragma unroll
        for (int s = 0; s < 2; s++) {
            const int cb = s * 8;
            const int lr = lane >> 2;
            const int lc = lane & 3;

            uint32_t Bfh[4][2], Bfl[4][2];
            #pragma unroll
            for (int ni = 0; ni < 4; ni++) {
                int n = warp_n + ni * 8 + lr;
                int o = n * SROW + cb + lc;
                Bfh[ni][0] = sB_hi[o];  Bfh[ni][1] = sB_hi[o + 4];
                Bfl[ni][0] = sB_lo[o];  Bfl[ni][1] = sB_lo[o + 4];
            }
            uint32_t Afh[4][4];
            #pragma unroll
            for (int mi = 0; mi < 4; mi++) {
                int m = warp_m + mi * 16 + lr;
                int o = m * SROW + cb + lc;
                Afh[mi][0] = sA_hi[o];
                Afh[mi][1] = sA_hi[o + 8 * SROW];
                Afh[mi][2] = sA_hi[o + 4];
                Afh[mi][3] = sA_hi[o + 8 * SROW + 4];
            }
            #pragma unroll
            for (int mi = 0; mi < 4; mi++)
                #pragma unroll
                for (int ni = 0; ni < 4; ni++)
                    mma_bf16(acc[mi][ni], Afh[mi], Bfh[ni]);
            #pragma unroll
            for (int mi = 0; mi < 4; mi++)
                #pragma unroll
                for (int ni = 0; ni < 4; ni++)
                    mma_bf16(acc[mi][ni], Afh[mi], Bfl[ni]);

            uint32_t Afl[4][4];
            #pragma unroll
            for (int mi = 0; mi < 4; mi++) {
                int m = warp_m + mi * 16 + lr;
                int o = m * SROW + cb + lc;
                Afl[mi][0] = sA_lo[o];
                Afl[mi][1] = sA_lo[o + 8 * SROW];
                Afl[mi][2] = sA_lo[o + 4];
                Afl[mi][3] = sA_lo[o + 8 * SROW + 4];
            }
            #pragma unroll
            for (int mi = 0; mi < 4; mi++)
                #pragma unroll
                for (int ni = 0; ni < 4; ni++)
                    mma_bf16(acc[mi][ni], Afl[mi], Bfh[ni]);
        }
        __syncthreads();
    }

    // ---- epilogue ----
    const int lr = lane >> 2;
    const int lc = lane & 3;
    #pragma unroll
    for (int mi = 0; mi < 4; mi++) {
        #pragma unroll
        for (int half = 0; half < 2; half++) {
            int gm = row0 + warp_m + mi * 16 + half * 8 + lr;
            if (gm >= M) continue;
            #pragma unroll
            for (int ni = 0; ni < 4; ni++) {
                int gn = col0 + warp_n + ni * 8 + lc * 2;
                float2 r;
                r.x = acc[mi][ni][half * 2 + 0];
                r.y = acc[mi][ni][half * 2 + 1];
                float2 bb = *(const float2*)(bias + gn);
                r.x += bb.x; r.y += bb.y;
                if (MODE != MODE_FINAL) {
                    r.x = fmaxf(r.x, 0.f);
                    r.y = fmaxf(r.y, 0.f);
                }
                if (MODE == MODE_RES) {
                    float2 a1 = *(const float2*)(A + (size_t)gm * DIM + gn);
                    r.x += a1.x; r.y += a1.y;
                }
                if (MODE == MODE_RES_POOL) {
                    float2 a2 = *(const float2*)(A + (size_t)gm * DIM + gn);
                    float2 hh = *(const float2*)(H1 + (size_t)gm * DIM + gn);
                    r.x = 0.5f * (r.x + a2.x + hh.x);
                    r.y = 0.5f * (r.y + a2.y + hh.y);
                }
                if (MODE == MODE_GIN || MODE == MODE_RES || MODE == MODE_FINAL)
                    *(float2*)(out + (size_t)gm * Nout + gn) = r;
                if (MODE == MODE_GIN || MODE == MODE_RES_POOL) {
                    uint32_t h, l;
                    split2(r.x, r.y, h, l);
                    size_t oidx = (size_t)gm * (Nout >> 1) + (gn >> 1);
                    outh[oidx] = h;
                    outl[oidx] = l;
                }
            }
        }
    }
}

// ---------------- launch ----------------
extern "C" void kernel_launch(void* const* d_in, const int* in_sizes, int n_in,
                              void* d_out, int out_size)
{
    const float* X    = (const float*)d_in[0];
    const void*  src  = d_in[1];
    const void*  dst  = d_in[2];
    const float* eps1 = (const float*)d_in[3];
    const float* W1   = (const float*)d_in[4];
    const float* b1   = (const float*)d_in[5];
    const float* rW1  = (const float*)d_in[6];
    const float* rb1  = (const float*)d_in[7];
    const float* eps2 = (const float*)d_in[8];
    const float* W2   = (const float*)d_in[9];
    const float* b2   = (const float*)d_in[10];
    const float* rW2  = (const float*)d_in[11];
    const float* rb2  = (const float*)d_in[12];
    const float* linW = (const float*)d_in[13];
    const float* linb = (const float*)d_in[14];
    float* out = (float*)d_out;

    const int M  = in_sizes[0] / DIM;   // 100000
    const int nE = in_sizes[1];         // 1600000 (elements if i32; see detect)

    float4 *abuf4, *h14;
    uint32_t *gih, *gil, *abh, *abl, *plh, *pll, *wbh, *wbl;
    cudaGetSymbolAddress((void**)&abuf4, g_abuf);
    cudaGetSymbolAddress((void**)&h14,   g_h1);
    cudaGetSymbolAddress((void**)&gih,   g_gin_h);
    cudaGetSymbolAddress((void**)&gil,   g_gin_l);
    cudaGetSymbolAddress((void**)&abh,   g_abuf_h);
    cudaGetSymbolAddress((void**)&abl,   g_abuf_l);
    cudaGetSymbolAddress((void**)&plh,   g_pool_h);
    cudaGetSymbolAddress((void**)&pll,   g_pool_l);
    cudaGetSymbolAddress((void**)&wbh,   g_wb_h);
    cudaGetSymbolAddress((void**)&wbl,   g_wb_l);
    float* abuf = (float*)abuf4;
    float* h1   = (float*)h14;

    cudaFuncSetAttribute(gemm_mma<MODE_GIN>,      cudaFuncAttributeMaxDynamicSharedMemorySize, SM_PIPE);
    cudaFuncSetAttribute(gemm_mma<MODE_RES>,      cudaFuncAttributeMaxDynamicSharedMemorySize, SM_PIPE);
    cudaFuncSetAttribute(gemm_mma<MODE_RES_POOL>, cudaFuncAttributeMaxDynamicSharedMemorySize, SM_PIPE);
    cudaFuncSetAttribute(gemm_mma<MODE_FINAL>,    cudaFuncAttributeMaxDynamicSharedMemorySize, SM_PIPE);

    const int mBlocks = (M + 127) / 128;
    dim3 g128(1, mBlocks);
    dim3 gfin(NUM_LABELS / 128, mBlocks);
    const int aggBlocks = (M * 32 + 255) / 256;

    detect_kernel<<<1, 32>>>((const unsigned long long*)src);

    // weight pre-splits
    split_w_kernel<<<(128 * 64 + 255) / 256, 256>>>(W1,   wbh + OFF_W1,  wbl + OFF_W1,  128);
    split_w_kernel<<<(128 * 64 + 255) / 256, 256>>>(rW1,  wbh + OFF_RW1, wbl + OFF_RW1, 128);
    split_w_kernel<<<(128 * 64 + 255) / 256, 256>>>(W2,   wbh + OFF_W2,  wbl + OFF_W2,  128);
    split_w_kernel<<<(128 * 64 + 255) / 256, 256>>>(rW2,  wbh + OFF_RW2, wbl + OFF_RW2, 128);
    split_w_kernel<<<(1024 * 64 + 255) / 256, 256>>>(linW, wbh + OFF_LIN, wbl + OFF_LIN, 1024);

    // ---- CSR build (shared by both layers) ----
    zero_deg_kernel<<<(M + 255) / 256, 256>>>(M);
    hist_kernel<<<2048, 256>>>(dst, nE);
    scan_kernel<<<1, 1024>>>(M);
    fill_kernel<<<2048, 256>>>(src, dst, nE);

    // ---- layer 1 ----
    agg_kernel<<<aggBlocks, 256>>>((const float4*)X, eps1, gih, gil, M);
    gemm_mma<MODE_GIN><<<g128, 256, SM_PIPE>>>(nullptr, gih, gil, nullptr,
                                               wbh + OFF_W1, wbl + OFF_W1, b1,
                                               abuf, abh, abl, M, DIM);
    gemm_mma<MODE_RES><<<g128, 256, SM_PIPE>>>(abuf, abh, abl, nullptr,
                                               wbh + OFF_RW1, wbl + OFF_RW1, rb1,
                                               h1, nullptr, nullptr, M, DIM);

    // ---- layer 2 ----
    agg_kernel<<<aggBlocks, 256>>>((const float4*)h1, eps2, gih, gil, M);
    gemm_mma<MODE_GIN><<<g128, 256, SM_PIPE>>>(nullptr, gih, gil, nullptr,
                                               wbh + OFF_W2, wbl + OFF_W2, b2,
                                               abuf, abh, abl, M, DIM);
    gemm_mma<MODE_RES_POOL><<<g128, 256, SM_PIPE>>>(abuf, abh, abl, h1,
                                                    wbh + OFF_RW2, wbl + OFF_RW2, rb2,
                                                    nullptr, plh, pll, M, DIM);

    // ---- head ----
    gemm_mma<MODE_FINAL><<<gfin, 256, SM_PIPE>>>(nullptr, plh, pll, nullptr,
                                                 wbh + OFF_LIN, wbl + OFF_LIN, linb,
                                                 out, nullptr, nullptr, M, NUM_LABELS);
}

// round 8
// speedup vs baseline: 2.2954x; 1.2537x over previous
#include <cuda_runtime.h>
#include <cuda_bf16.h>
#include <cuda_fp16.h>
#include <cstdint>

#define N_NODES 100000
#define NPAD    100096
#define DIM 128
#define NUM_LABELS 1024
#define MAX_E 1700000

// ---------------- scratch ----------------
__device__ float4   g_h1  [ (size_t)N_NODES * (DIM/4) ];
__device__ uint32_t g_gin_h [(size_t)NPAD * 64];   // bf16-split GIN GEMM input
__device__ uint32_t g_gin_l [(size_t)NPAD * 64];
__device__ uint32_t g_pool_h[(size_t)NPAD * 64];   // fp16-split pool (head input)
__device__ uint32_t g_pool_l[(size_t)NPAD * 64];
// CSR by dst
__device__ int g_deg   [NPAD];
__device__ int g_rowptr[NPAD + 1];
__device__ int g_cursor[NPAD];
__device__ int g_csrsrc[MAX_E];
// pre-split transposed weights (bf16 x4 small, fp16-hi for lin)
#define OFF_W1  0
#define OFF_RW1 8192
#define OFF_W2  16384
#define OFF_RW2 24576
#define OFF_LIN 32768
__device__ uint32_t g_wb_h[98304];
__device__ uint32_t g_wb_l[32768];
__device__ int      g_idx64;

// ---------------- helpers ----------------
__device__ __forceinline__ uint32_t smem_to_u32(const void* p) {
    uint32_t a;
    asm("{ .reg .u64 t; cvta.to.shared.u64 t, %1; cvt.u32.u64 %0, t; }" : "=r"(a) : "l"(p));
    return a;
}
__device__ __forceinline__ void split2(float x, float y, uint32_t& hi, uint32_t& lo) {
    __nv_bfloat16 hx = __float2bfloat16(x);
    __nv_bfloat16 hy = __float2bfloat16(y);
    __nv_bfloat16 lx = __float2bfloat16(x - __bfloat162float(hx));
    __nv_bfloat16 ly = __float2bfloat16(y - __bfloat162float(hy));
    hi = ((uint32_t)__bfloat16_as_ushort(hy) << 16) | (uint32_t)__bfloat16_as_ushort(hx);
    lo = ((uint32_t)__bfloat16_as_ushort(ly) << 16) | (uint32_t)__bfloat16_as_ushort(lx);
}
__device__ __forceinline__ void split2h(float x, float y, uint32_t& hi, uint32_t& lo) {
    __half hx = __float2half_rn(x);
    __half hy = __float2half_rn(y);
    __half lx = __float2half_rn(x - __half2float(hx));
    __half ly = __float2half_rn(y - __half2float(hy));
    hi = ((uint32_t)__half_as_ushort(hy) << 16) | (uint32_t)__half_as_ushort(hx);
    lo = ((uint32_t)__half_as_ushort(ly) << 16) | (uint32_t)__half_as_ushort(lx);
}
__device__ __forceinline__ float bf_lo(uint32_t v) {
    return __bfloat162float(__ushort_as_bfloat16((unsigned short)(v & 0xFFFF)));
}
__device__ __forceinline__ float bf_hi(uint32_t v) {
    return __bfloat162float(__ushort_as_bfloat16((unsigned short)(v >> 16)));
}
__device__ __forceinline__ void mma_bf16(float* d, const uint32_t* a, const uint32_t* b) {
    asm volatile(
        "mma.sync.aligned.m16n8k16.row.col.f32.bf16.bf16.f32 "
        "{%0,%1,%2,%3}, {%4,%5,%6,%7}, {%8,%9}, {%0,%1,%2,%3};"
        : "+f"(d[0]), "+f"(d[1]), "+f"(d[2]), "+f"(d[3])
        : "r"(a[0]), "r"(a[1]), "r"(a[2]), "r"(a[3]), "r"(b[0]), "r"(b[1]));
}
__device__ __forceinline__ void mma_f16(float* d, const uint32_t* a, const uint32_t* b) {
    asm volatile(
        "mma.sync.aligned.m16n8k16.row.col.f32.f16.f16.f32 "
        "{%0,%1,%2,%3}, {%4,%5,%6,%7}, {%8,%9}, {%0,%1,%2,%3};"
        : "+f"(d[0]), "+f"(d[1]), "+f"(d[2]), "+f"(d[3])
        : "r"(a[0]), "r"(a[1]), "r"(a[2]), "r"(a[3]), "r"(b[0]), "r"(b[1]));
}
#define CPA16(dst, src) \
    asm volatile("cp.async.ca.shared.global [%0], [%1], 16;" :: "r"(dst), "l"(src) : "memory")

__device__ __forceinline__ long long edge_idx(const void* p, int i) {
    return g_idx64 ? ((const long long*)p)[i] : (long long)((const int*)p)[i];
}

// ---------------- index-width detection ----------------
__global__ void detect_kernel(const unsigned long long* __restrict__ src) {
    if (threadIdx.x == 0 && blockIdx.x == 0) {
        int is64 = 1;
        for (int i = 0; i < 64; i++) {
            if (src[i] >> 32) { is64 = 0; break; }
        }
        g_idx64 = is64;
    }
}

// ---------------- CSR build ----------------
__global__ void zero_deg_kernel(int n) {
    int i = blockIdx.x * blockDim.x + threadIdx.x;
    if (i < n) g_deg[i] = 0;
}
__global__ void hist_kernel(const void* __restrict__ dstv, int nE) {
    int i = blockIdx.x * blockDim.x + threadIdx.x;
    int stride = gridDim.x * blockDim.x;
    for (; i < nE; i += stride) {
        int d = (int)edge_idx(dstv, i);
        atomicAdd(&g_deg[d], 1);
    }
}
__global__ __launch_bounds__(1024) void scan_kernel(int n) {
    __shared__ int ssum[1024];
    int t = threadIdx.x;
    int chunk = (n + 1023) / 1024;
    int b = t * chunk;
    int e = min(b + chunk, n);
    int s = 0;
    for (int i = b; i < e; i++) s += g_deg[i];
    ssum[t] = s;
    __syncthreads();
    for (int off = 1; off < 1024; off <<= 1) {
        int v = (t >= off) ? ssum[t - off] : 0;
        __syncthreads();
        ssum[t] += v;
        __syncthreads();
    }
    int ex = (t == 0) ? 0 : ssum[t - 1];
    for (int i = b; i < e; i++) {
        g_rowptr[i] = ex;
        g_cursor[i] = ex;
        ex += g_deg[i];
    }
    if (t == 0) g_rowptr[n] = ssum[1023];
}
__global__ void fill_kernel(const void* __restrict__ srcv,
                            const void* __restrict__ dstv, int nE) {
    int i = blockIdx.x * blockDim.x + threadIdx.x;
    int stride = gridDim.x * blockDim.x;
    for (; i < nE; i += stride) {
        int d = (int)edge_idx(dstv, i);
        int s = (int)edge_idx(srcv, i);
        int pos = atomicAdd(&g_cursor[d], 1);
        g_csrsrc[pos] = s;
    }
}

// ---------------- aggregation: one warp per node ----------------
__global__ void agg_kernel(const float4* __restrict__ h,
                           const float* __restrict__ epsp,
                           uint32_t* __restrict__ outh,
                           uint32_t* __restrict__ outl,
                           int M)
{
    int node = (blockIdx.x * blockDim.x + threadIdx.x) >> 5;
    int lane = threadIdx.x & 31;
    if (node >= M) return;
    const float eps1 = 1.0f + epsp[0];

    float4 acc = h[(size_t)node * 32 + lane];
    acc.x *= eps1; acc.y *= eps1; acc.z *= eps1; acc.w *= eps1;

    int e   = g_rowptr[node];
    int end = g_rowptr[node + 1];
    for (; e + 4 <= end; e += 4) {
        int s0 = g_csrsrc[e], s1 = g_csrsrc[e + 1], s2 = g_csrsrc[e + 2], s3 = g_csrsrc[e + 3];
        float4 v0 = h[(size_t)s0 * 32 + lane];
        float4 v1 = h[(size_t)s1 * 32 + lane];
        float4 v2 = h[(size_t)s2 * 32 + lane];
        float4 v3 = h[(size_t)s3 * 32 + lane];
        acc.x += v0.x + v1.x + v2.x + v3.x;
        acc.y += v0.y + v1.y + v2.y + v3.y;
        acc.z += v0.z + v1.z + v2.z + v3.z;
        acc.w += v0.w + v1.w + v2.w + v3.w;
    }
    for (; e < end; e++) {
        int s = g_csrsrc[e];
        float4 v = h[(size_t)s * 32 + lane];
        acc.x += v.x; acc.y += v.y; acc.z += v.z; acc.w += v.w;
    }

    uint32_t h0, l0, h1v, l1v;
    split2(acc.x, acc.y, h0, l0);
    split2(acc.z, acc.w, h1v, l1v);
    size_t o = (size_t)node * 64 + lane * 2;
    *(uint2*)&outh[o] = make_uint2(h0, h1v);
    *(uint2*)&outl[o] = make_uint2(l0, l1v);
}

// ---------------- weight pre-splits ----------------
__global__ void split_w_kernel(const float* __restrict__ W,
                               uint32_t* __restrict__ hi, uint32_t* __restrict__ lo,
                               int Nout)
{
    int t = blockIdx.x * blockDim.x + threadIdx.x;
    if (t >= Nout * 64) return;
    int n = t % Nout;
    int p = t / Nout;
    float x = W[(size_t)(2 * p)     * Nout + n];
    float y = W[(size_t)(2 * p + 1) * Nout + n];
    uint32_t h, l;
    split2(x, y, h, l);
    int chunk = p >> 4, j = p & 15;
    hi[((size_t)chunk * Nout + n) * 16 + j] = h;
    lo[((size_t)chunk * Nout + n) * 16 + j] = l;
}
__global__ void split_w_f16_kernel(const float* __restrict__ W,
                                   uint32_t* __restrict__ hi, int Nout)
{
    int t = blockIdx.x * blockDim.x + threadIdx.x;
    if (t >= Nout * 64) return;
    int n = t % Nout;
    int p = t / Nout;
    __half x = __float2half_rn(W[(size_t)(2 * p)     * Nout + n]);
    __half y = __float2half_rn(W[(size_t)(2 * p + 1) * Nout + n]);
    uint32_t h = ((uint32_t)__half_as_ushort(y) << 16) | (uint32_t)__half_as_ushort(x);
    int chunk = p >> 4, j = p & 15;
    hi[((size_t)chunk * Nout + n) * 16 + j] = h;
}

// ======================= fused layer kernel ===================================
// Phase1: T = relu( A(split bf16) @ W + b )   (T = 128x128 block-local, to smem)
// Phase2: acc2 = T @ rW ; epilogue:
//   LAYER 0: h1 = T + relu(acc2 + rb)                      -> h1 fp32
//   LAYER 1: pool = 0.5*(h1 + T + relu(acc2 + rb))         -> fp16 hi/lo split
#define SROW 20
#define TROW 68
#define TILE_U32 (128 * SROW)
#define SM_FUSED 110592    // max(2*4*TILE*4, 4*TILE*4 + 2*128*TROW*4)

template <int LAYER>
__global__ __launch_bounds__(256)
void fused_layer(const uint32_t* __restrict__ Ah,
                 const uint32_t* __restrict__ Al,
                 const uint32_t* __restrict__ Wh,
                 const uint32_t* __restrict__ Wl,
                 const float* __restrict__ b,
                 const uint32_t* __restrict__ rWh,
                 const uint32_t* __restrict__ rWl,
                 const float* __restrict__ rb,
                 float* __restrict__ h1io,        // LAYER0: write; LAYER1: read
                 uint32_t* __restrict__ poolh,
                 uint32_t* __restrict__ pooll,
                 int M)
{
    extern __shared__ uint32_t smem_u[];
    const int tid  = threadIdx.x;
    const int wid  = tid >> 5;
    const int lane = tid & 31;
    const int row0 = blockIdx.y * 128;
    const int warp_m = (wid & 1) * 64;
    const int warp_n = (wid >> 1) * 32;
    const uint32_t sbase = smem_to_u32(smem_u);
    const int lr = lane >> 2;
    const int lc = lane & 3;

    // phase2 smem layout
    uint32_t* sB2   = smem_u;                        // 2 stages x 2 tiles
    uint32_t* sTh   = smem_u + 4 * TILE_U32;         // 128 x TROW
    uint32_t* sTl   = sTh + 128 * TROW;

    float acc[4][4][4];
    #pragma unroll
    for (int mi = 0; mi < 4; mi++)
        #pragma unroll
        for (int ni = 0; ni < 4; ni++)
            #pragma unroll
            for (int r = 0; r < 4; r++) acc[mi][ni][r] = 0.f;

    // ---- phase1 cp.async: A (gin split) + W tiles ----
    auto issue1 = [&](int c, int stage) {
        #pragma unroll
        for (int i = 0; i < 8; i++) {
            int idx  = tid + i * 256;
            int tile = idx >> 9;
            int r    = idx & 511;
            int row  = r >> 2;
            int j4   = r & 3;
            const uint32_t* g;
            if (tile == 0)      g = Ah + (size_t)(row0 + row) * 64 + c * 16 + j4 * 4;
            else if (tile == 1) g = Al + (size_t)(row0 + row) * 64 + c * 16 + j4 * 4;
            else if (tile == 2) g = Wh + ((size_t)c * 128 + row) * 16 + j4 * 4;
            else                g = Wl + ((size_t)c * 128 + row) * 16 + j4 * 4;
            uint32_t d = sbase + (uint32_t)(stage * 4 * TILE_U32 + tile * TILE_U32 + row * SROW + j4 * 4) * 4;
            CPA16(d, g);
        }
        asm volatile("cp.async.commit_group;" ::: "memory");
    };

    auto mma_block = [&](const uint32_t* sA_hi, const uint32_t* sA_lo,
                         const uint32_t* sB_hi, const uint32_t* sB_lo,
                         int arow_stride, int acol0) {
        #pragma unroll
        for (int s = 0; s < 2; s++) {
            const int cb = s * 8;
            uint32_t Bfh[4][2], Bfl[4][2];
            #pragma unroll
            for (int ni = 0; ni < 4; ni++) {
                int n = warp_n + ni * 8 + lr;
                int o = n * SROW + cb + lc;
                Bfh[ni][0] = sB_hi[o];  Bfh[ni][1] = sB_hi[o + 4];
                Bfl[ni][0] = sB_lo[o];  Bfl[ni][1] = sB_lo[o + 4];
            }
            uint32_t Afh[4][4];
            #pragma unroll
            for (int mi = 0; mi < 4; mi++) {
                int m = warp_m + mi * 16 + lr;
                int o = m * arow_stride + acol0 + cb + lc;
                Afh[mi][0] = sA_hi[o];
                Afh[mi][1] = sA_hi[o + 8 * arow_stride];
                Afh[mi][2] = sA_hi[o + 4];
                Afh[mi][3] = sA_hi[o + 8 * arow_stride + 4];
            }
            #pragma unroll
            for (int mi = 0; mi < 4; mi++)
                #pragma unroll
                for (int ni = 0; ni < 4; ni++)
                    mma_bf16(acc[mi][ni], Afh[mi], Bfh[ni]);
            #pragma unroll
            for (int mi = 0; mi < 4; mi++)
                #pragma unroll
                for (int ni = 0; ni < 4; ni++)
                    mma_bf16(acc[mi][ni], Afh[mi], Bfl[ni]);
            uint32_t Afl[4][4];
            #pragma unroll
            for (int mi = 0; mi < 4; mi++) {
                int m = warp_m + mi * 16 + lr;
                int o = m * arow_stride + acol0 + cb + lc;
                Afl[mi][0] = sA_lo[o];
                Afl[mi][1] = sA_lo[o + 8 * arow_stride];
                Afl[mi][2] = sA_lo[o + 4];
                Afl[mi][3] = sA_lo[o + 8 * arow_stride + 4];
            }
            #pragma unroll
            for (int mi = 0; mi < 4; mi++)
                #pragma unroll
                for (int ni = 0; ni < 4; ni++)
                    mma_bf16(acc[mi][ni], Afl[mi], Bfh[ni]);
        }
    };

    // ================= phase 1 =================
    issue1(0, 0);
    #pragma unroll 1
    for (int c = 0; c < 4; c++) {
        const int stage = c & 1;
        uint32_t* st = smem_u + stage * 4 * TILE_U32;
        if (c + 1 < 4) {
            issue1(c + 1, (c + 1) & 1);
            asm volatile("cp.async.wait_group 1;" ::: "memory");
        } else {
            asm volatile("cp.async.wait_group 0;" ::: "memory");
        }
        __syncthreads();
        mma_block(st, st + TILE_U32, st + 2 * TILE_U32, st + 3 * TILE_U32, SROW, 0);
        __syncthreads();
    }

    // ---- phase2 B prefetch chunk 0 ----
    auto issue2 = [&](int c, int stage) {
        #pragma unroll
        for (int i = 0; i < 4; i++) {
            int idx  = tid + i * 256;
            int tile = idx >> 9;     // 0 hi, 1 lo
            int r    = idx & 511;
            int row  = r >> 2;
            int j4   = r & 3;
            const uint32_t* g = (tile ? rWl : rWh) + ((size_t)c * 128 + row) * 16 + j4 * 4;
            uint32_t d = sbase + (uint32_t)(stage * 2 * TILE_U32 + tile * TILE_U32 + row * SROW + j4 * 4) * 4;
            CPA16(d, g);
        }
        asm volatile("cp.async.commit_group;" ::: "memory");
    };
    issue2(0, 0);

    // ---- epilogue1: T = relu(acc + b) -> smem split; re-zero acc ----
    #pragma unroll
    for (int mi = 0; mi < 4; mi++) {
        #pragma unroll
        for (int half = 0; half < 2; half++) {
            int m = warp_m + mi * 16 + half * 8 + lr;
            #pragma unroll
            for (int ni = 0; ni < 4; ni++) {
                int gn = warp_n + ni * 8 + lc * 2;
                float2 bb = *(const float2*)(b + gn);
                float tx = fmaxf(acc[mi][ni][half * 2 + 0] + bb.x, 0.f);
                float ty = fmaxf(acc[mi][ni][half * 2 + 1] + bb.y, 0.f);
                uint32_t h, l;
                split2(tx, ty, h, l);
                int o = m * TROW + (warp_n >> 1) + ni * 4 + lc;
                sTh[o] = h;
                sTl[o] = l;
            }
        }
    }
    #pragma unroll
    for (int mi = 0; mi < 4; mi++)
        #pragma unroll
        for (int ni = 0; ni < 4; ni++)
            #pragma unroll
            for (int r = 0; r < 4; r++) acc[mi][ni][r] = 0.f;
    __syncthreads();

    // ================= phase 2: acc = T @ rW =================
    #pragma unroll 1
    for (int c = 0; c < 4; c++) {
        const int stage = c & 1;
        uint32_t* st = sB2 + stage * 2 * TILE_U32;
        if (c + 1 < 4) {
            issue2(c + 1, (c + 1) & 1);
            asm volatile("cp.async.wait_group 1;" ::: "memory");
        } else {
            asm volatile("cp.async.wait_group 0;" ::: "memory");
        }
        __syncthreads();
        mma_block(sTh, sTl, st, st + TILE_U32, TROW, c * 16);
        __syncthreads();
    }

    // ---- epilogue2 ----
    #pragma unroll
    for (int mi = 0; mi < 4; mi++) {
        #pragma unroll
        for (int half = 0; half < 2; half++) {
            int m  = warp_m + mi * 16 + half * 8 + lr;
            int gm = row0 + m;
            if (gm >= M) continue;
            #pragma unroll
            for (int ni = 0; ni < 4; ni++) {
                int gn = warp_n + ni * 8 + lc * 2;
                float2 rr;
                float2 bb = *(const float2*)(rb + gn);
                rr.x = fmaxf(acc[mi][ni][half * 2 + 0] + bb.x, 0.f);
                rr.y = fmaxf(acc[mi][ni][half * 2 + 1] + bb.y, 0.f);
                int o = m * TROW + (warp_n >> 1) + ni * 4 + lc;
                uint32_t th = sTh[o], tl = sTl[o];
                float tx = bf_lo(th) + bf_lo(tl);
                float ty = bf_hi(th) + bf_hi(tl);
                if (LAYER == 0) {
                    rr.x += tx; rr.y += ty;
                    *(float2*)(h1io + (size_t)gm * DIM + gn) = rr;
                } else {
                    float2 hh = *(const float2*)(h1io + (size_t)gm * DIM + gn);
                    rr.x = 0.5f * (rr.x + tx + hh.x);
                    rr.y = 0.5f * (rr.y + ty + hh.y);
                    uint32_t ph, pl;
                    split2h(rr.x, rr.y, ph, pl);
                    size_t oidx = (size_t)gm * 64 + (gn >> 1);
                    poolh[oidx] = ph;
                    pooll[oidx] = pl;
                }
            }
        }
    }
}

// ======================= head GEMM: fp16 2-term ==============================
#define SM_HEAD (2 * 3 * TILE_U32 * 4)   // 61440

__global__ __launch_bounds__(256)
void gemm_head(const uint32_t* __restrict__ Ah,
               const uint32_t* __restrict__ Al,
               const uint32_t* __restrict__ Bh,
               const float* __restrict__ bias,
               float* __restrict__ out,
               int M)
{
    extern __shared__ uint32_t smem_u[];
    const int tid  = threadIdx.x;
    const int wid  = tid >> 5;
    const int lane = tid & 31;
    const int row0 = blockIdx.y * 128;
    const int col0 = blockIdx.x * 128;
    const int warp_m = (wid & 1) * 64;
    const int warp_n = (wid >> 1) * 32;
    const uint32_t sbase = smem_to_u32(smem_u);
    const int lr = lane >> 2;
    const int lc = lane & 3;

    float acc[4][4][4];
    #pragma unroll
    for (int mi = 0; mi < 4; mi++)
        #pragma unroll
        for (int ni = 0; ni < 4; ni++)
            #pragma unroll
            for (int r = 0; r < 4; r++) acc[mi][ni][r] = 0.f;

    auto issue = [&](int c, int stage) {
        #pragma unroll
        for (int i = 0; i < 6; i++) {
            int idx  = tid + i * 256;       // 0..1535
            int tile = idx / 512;           // 0 Ah, 1 Al, 2 Bh
            int r    = idx & 511;
            int row  = r >> 2;
            int j4   = r & 3;
            const uint32_t* g;
            if (tile == 0)      g = Ah + (size_t)(row0 + row) * 64 + c * 16 + j4 * 4;
            else if (tile == 1) g = Al + (size_t)(row0 + row) * 64 + c * 16 + j4 * 4;
            else                g = Bh + ((size_t)c * NUM_LABELS + col0 + row) * 16 + j4 * 4;
            uint32_t d = sbase + (uint32_t)(stage * 3 * TILE_U32 + tile * TILE_U32 + row * SROW + j4 * 4) * 4;
            CPA16(d, g);
        }
        asm volatile("cp.async.commit_group;" ::: "memory");
    };

    issue(0, 0);
    #pragma unroll 1
    for (int c = 0; c < 4; c++) {
        const int stage = c & 1;
        uint32_t* sA_hi = smem_u + stage * 3 * TILE_U32;
        uint32_t* sA_lo = sA_hi + TILE_U32;
        uint32_t* sB_hi = sA_hi + 2 * TILE_U32;
        if (c + 1 < 4) {
            issue(c + 1, (c + 1) & 1);
            asm volatile("cp.async.wait_group 1;" ::: "memory");
        } else {
            asm volatile("cp.async.wait_group 0;" ::: "memory");
        }
        __syncthreads();

        #pragma unroll
        for (int s = 0; s < 2; s++) {
            const int cb = s * 8;
            uint32_t Bf[4][2];
            #pragma unroll
            for (int ni = 0; ni < 4; ni++) {
                int n = warp_n + ni * 8 + lr;
                int o = n * SROW + cb + lc;
                Bf[ni][0] = sB_hi[o];  Bf[ni][1] = sB_hi[o + 4];
            }
            uint32_t Afh[4][4], Afl[4][4];
            #pragma unroll
            for (int mi = 0; mi < 4; mi++) {
                int m = warp_m + mi * 16 + lr;
                int o = m * SROW + cb + lc;
                Afh[mi][0] = sA_hi[o];
                Afh[mi][1] = sA_hi[o + 8 * SROW];
                Afh[mi][2] = sA_hi[o + 4];
                Afh[mi][3] = sA_hi[o + 8 * SROW + 4];
                Afl[mi][0] = sA_lo[o];
                Afl[mi][1] = sA_lo[o + 8 * SROW];
                Afl[mi][2] = sA_lo[o + 4];
                Afl[mi][3] = sA_lo[o + 8 * SROW + 4];
            }
            #pragma unroll
            for (int mi = 0; mi < 4; mi++)
                #pragma unroll
                for (int ni = 0; ni < 4; ni++)
                    mma_f16(acc[mi][ni], Afh[mi], Bf[ni]);
            #pragma unroll
            for (int mi = 0; mi < 4; mi++)
                #pragma unroll
                for (int ni = 0; ni < 4; ni++)
                    mma_f16(acc[mi][ni], Afl[mi], Bf[ni]);
        }
        __syncthreads();
    }

    #pragma unroll
    for (int mi = 0; mi < 4; mi++) {
        #pragma unroll
        for (int half = 0; half < 2; half++) {
            int gm = row0 + warp_m + mi * 16 + half * 8 + lr;
            if (gm >= M) continue;
            #pragma unroll
            for (int ni = 0; ni < 4; ni++) {
                int gn = col0 + warp_n + ni * 8 + lc * 2;
                float2 r;
                float2 bb = *(const float2*)(bias + gn);
                r.x = acc[mi][ni][half * 2 + 0] + bb.x;
                r.y = acc[mi][ni][half * 2 + 1] + bb.y;
                *(float2*)(out + (size_t)gm * NUM_LABELS + gn) = r;
            }
        }
    }
}

// ---------------- launch ----------------
extern "C" void kernel_launch(void* const* d_in, const int* in_sizes, int n_in,
                              void* d_out, int out_size)
{
    const float* X    = (const float*)d_in[0];
    const void*  src  = d_in[1];
    const void*  dst  = d_in[2];
    const float* eps1 = (const float*)d_in[3];
    const float* W1   = (const float*)d_in[4];
    const float* b1   = (const float*)d_in[5];
    const float* rW1  = (const float*)d_in[6];
    const float* rb1  = (const float*)d_in[7];
    const float* eps2 = (const float*)d_in[8];
    const float* W2   = (const float*)d_in[9];
    const float* b2   = (const float*)d_in[10];
    const float* rW2  = (const float*)d_in[11];
    const float* rb2  = (const float*)d_in[12];
    const float* linW = (const float*)d_in[13];
    const float* linb = (const float*)d_in[14];
    float* out = (float*)d_out;

    const int M  = in_sizes[0] / DIM;   // 100000
    const int nE = in_sizes[1];         // 1600000

    float4* h14;
    uint32_t *gih, *gil, *plh, *pll, *wbh, *wbl;
    cudaGetSymbolAddress((void**)&h14, g_h1);
    cudaGetSymbolAddress((void**)&gih, g_gin_h);
    cudaGetSymbolAddress((void**)&gil, g_gin_l);
    cudaGetSymbolAddress((void**)&plh, g_pool_h);
    cudaGetSymbolAddress((void**)&pll, g_pool_l);
    cudaGetSymbolAddress((void**)&wbh, g_wb_h);
    cudaGetSymbolAddress((void**)&wbl, g_wb_l);
    float* h1 = (float*)h14;

    cudaFuncSetAttribute(fused_layer<0>, cudaFuncAttributeMaxDynamicSharedMemorySize, SM_FUSED);
    cudaFuncSetAttribute(fused_layer<1>, cudaFuncAttributeMaxDynamicSharedMemorySize, SM_FUSED);
    cudaFuncSetAttribute(gemm_head,      cudaFuncAttributeMaxDynamicSharedMemorySize, SM_HEAD);

    const int mBlocks = (M + 127) / 128;
    dim3 gfuse(1, mBlocks);
    dim3 ghead(NUM_LABELS / 128, mBlocks);
    const int aggBlocks = (M * 32 + 255) / 256;

    detect_kernel<<<1, 32>>>((const unsigned long long*)src);

    split_w_kernel<<<(128 * 64 + 255) / 256, 256>>>(W1,  wbh + OFF_W1,  wbl + OFF_W1,  128);
    split_w_kernel<<<(128 * 64 + 255) / 256, 256>>>(rW1, wbh + OFF_RW1, wbl + OFF_RW1, 128);
    split_w_kernel<<<(128 * 64 + 255) / 256, 256>>>(W2,  wbh + OFF_W2,  wbl + OFF_W2,  128);
    split_w_kernel<<<(128 * 64 + 255) / 256, 256>>>(rW2, wbh + OFF_RW2, wbl + OFF_RW2, 128);
    split_w_f16_kernel<<<(1024 * 64 + 255) / 256, 256>>>(linW, wbh + OFF_LIN, 1024);

    zero_deg_kernel<<<(M + 255) / 256, 256>>>(M);
    hist_kernel<<<2048, 256>>>(dst, nE);
    scan_kernel<<<1, 1024>>>(M);
    fill_kernel<<<2048, 256>>>(src, dst, nE);

    // layer 1
    agg_kernel<<<aggBlocks, 256>>>((const float4*)X, eps1, gih, gil, M);
    fused_layer<0><<<gfuse, 256, SM_FUSED>>>(gih, gil,
                                             wbh + OFF_W1, wbl + OFF_W1, b1,
                                             wbh + OFF_RW1, wbl + OFF_RW1, rb1,
                                             h1, nullptr, nullptr, M);
    // layer 2
    agg_kernel<<<aggBlocks, 256>>>((const float4*)h1, eps2, gih, gil, M);
    fused_layer<1><<<gfuse, 256, SM_FUSED>>>(gih, gil,
                                             wbh + OFF_W2, wbl + OFF_W2, b2,
                                             wbh + OFF_RW2, wbl + OFF_RW2, rb2,
                                             h1, plh, pll, M);
    // head
    gemm_head<<<ghead, 256, SM_HEAD>>>(plh, pll, wbh + OFF_LIN, linb, out, M);
}